// round 15
// baseline (speedup 1.0000x reference)
#include <cuda_runtime.h>
#include <math.h>

#define L 512
#define NCON 20
#define INV_TEMP (1.0f / 0.07f)
#define MAXROWS 32768
#define SD_BLOCKS 592   // 4 blocks/SM on 148 SMs
#define SD_THREADS 256
#define WPB (SD_THREADS / 32)
#define FULLMASK 0xffffffffu

// scratch (device globals; no allocation allowed)
// cnt arrays: zero-initialized at load; reset-on-consume in the row kernel
// keeps them all-zero at the start of every replay.
__device__ int   g_cnt0[MAXROWS];        // histogram of sz_idx
__device__ int   g_cnt1[MAXROWS];        // histogram of nsz_idx
__device__ float g_pB[SD_BLOCKS];        // per-block partials
__device__ unsigned int g_fin = 0;       // finalize counter (reset by last block)

// ---------------------------------------------------------------------------
// Kernel 1: index histograms (deterministic int atomics).
// ---------------------------------------------------------------------------
__global__ void hist_kernel(const int* __restrict__ sz_idx, int Ns,
                            const int* __restrict__ nsz_idx, int Nn, int Bs) {
    int b = blockIdx.x;
    int branch = (b >= Bs) ? 1 : 0;
    int i = (branch ? (b - Bs) : b) * (int)blockDim.x + threadIdx.x;
    if (branch) {
        if (i < Nn) atomicAdd(&g_cnt1[nsz_idx[i]], 1);
    } else {
        if (i < Ns) atomicAdd(&g_cnt0[sz_idx[i]], 1);
    }
}

// ---------------------------------------------------------------------------
// Kernel 2: branch-split row-driven pass with ballot skip + finalize.
// Blocks [0,Bh) -> branch 0 rows, [Bh,grid) -> branch 1. Per warp: lane l
// owns row wg + (l + 32k)*nw; all 32 cnt loads issue at once (MLP=32), rows
// are reset-on-consume, and the warp processes only nonzero-ballot rows:
//   acc += c * (log den - <row,ebar>*invn/tau) * scale
// ~60% of rows are skipped at zero cost -> ~52MB sequential DRAM traffic.
// Deterministic: fixed lane->row map, fixed ballot order, fixed trees,
// fixed-order last-block finalize.
// ---------------------------------------------------------------------------
__global__ void __launch_bounds__(SD_THREADS)
rowpass_kernel(const float* __restrict__ hg, int nrows,
               const float* __restrict__ corr,
               const float* __restrict__ all_emb,
               const int* __restrict__ Psz, int nPsz,
               const int* __restrict__ Pnsz, int nPnsz,
               int Bh, float invNs, float invNn,
               float* __restrict__ out) {
    __shared__ float se[L];
    __shared__ int sp[16];
    __shared__ float sw[WPB];
    __shared__ float sh[SD_THREADS];
    __shared__ bool is_last;

    int tid = threadIdx.x;
    int branch = (blockIdx.x >= Bh) ? 1 : 0;
    const int* P = branch ? Pnsz : Psz;
    int nP = branch ? nPnsz : nPsz;
    int* cntp = branch ? g_cnt1 : g_cnt0;
    float scale = branch ? invNn : invNs;

    if (tid < nP) sp[tid] = P[tid];
    __syncthreads();

    unsigned int mask = 0u;
    for (int j = 0; j < nP; j++) mask |= 1u << sp[j];

    // build this branch's ebar into smem (nP L2-hot concept rows)
    for (int t = tid; t < L; t += SD_THREADS) {
        float s = 0.0f;
        for (int j = 0; j < nP; j++) s += all_emb[sp[j] * L + t];
        se[t] = s / (float)nP;
    }
    __syncthreads();

    int lane = tid & 31;
    int wib  = tid >> 5;
    int bb   = branch ? (blockIdx.x - Bh) : blockIdx.x;
    int nbb  = branch ? (gridDim.x - Bh) : Bh;
    int wg   = bb * WPB + wib;    // warp index within branch
    int nw   = nbb * WPB;         // warps in branch

    const float4* ep = reinterpret_cast<const float4*>(se);
    bool act = lane < NCON;
    float wm = (act && !((mask >> lane) & 1u)) ? 1.0f : 0.0f;

    float acc = 0.0f;
    // outer loop over batches of 32 candidate rows per warp
    for (int k = 0; ; k++) {
        int myrow = wg + (lane + 32 * k) * nw;
        bool inb = (myrow < nrows);
        if (!__any_sync(FULLMASK, inb)) break;

        int c = inb ? cntp[myrow] : 0;          // 32 independent loads (MLP=32)
        if (c) cntp[myrow] = 0;                  // reset-on-consume (parallel)
        unsigned int bal = __ballot_sync(FULLMASK, c != 0);

        while (bal) {
            int b = __ffs(bal) - 1;
            bal &= bal - 1;
            int row = wg + (b + 32 * k) * nw;
            int cb  = __shfl_sync(FULLMASK, c, b);

            // denominator: lanes 0..19 handle one concept each
            float e = act ? __expf(corr[row * NCON + lane] * INV_TEMP) : 0.0f;
            float den = e * wm;

            const float4* rp = reinterpret_cast<const float4*>(hg + (size_t)row * L);
            float ss = 0.0f, d = 0.0f;
#pragma unroll
            for (int it = 0; it < 4; it++) {
                int idx = it * 32 + lane;
                float4 v  = rp[idx];
                float4 ev = ep[idx];
                ss = fmaf(v.x, v.x, fmaf(v.y, v.y, fmaf(v.z, v.z, fmaf(v.w, v.w, ss))));
                d  = fmaf(v.x, ev.x, fmaf(v.y, ev.y, fmaf(v.z, ev.z, fmaf(v.w, ev.w, d))));
            }
#pragma unroll
            for (int o = 16; o > 0; o >>= 1) {
                ss  += __shfl_xor_sync(FULLMASK, ss, o);
                d   += __shfl_xor_sync(FULLMASK, d, o);
                den += __shfl_xor_sync(FULLMASK, den, o);
            }
            if (lane == 0) {
                float invn = 1.0f / fmaxf(sqrtf(ss), 1e-12f);
                acc += (float)cb * (__logf(den) - d * invn * INV_TEMP) * scale;
            }
        }
    }

    // block partial + last-block fixed-order finalize
    if (lane == 0) sw[wib] = acc;
    __syncthreads();
    if (tid == 0) {
        float s = 0.0f;
#pragma unroll
        for (int k = 0; k < WPB; k++) s += sw[k];
        g_pB[blockIdx.x] = s;
        __threadfence();
        is_last = (atomicAdd(&g_fin, 1u) == gridDim.x - 1);
    }
    __syncthreads();

    if (is_last) {
        __threadfence();  // see all blocks' partials
        float a = 0.0f;
        for (int j = tid; j < SD_BLOCKS; j += SD_THREADS) a += g_pB[j];  // fixed order
        sh[tid] = a;
        __syncthreads();
        for (int s = 128; s > 0; s >>= 1) {
            if (tid < s) sh[tid] += sh[tid + s];
            __syncthreads();
        }
        if (tid == 0) { out[0] = sh[0]; g_fin = 0u; }
    }
}

extern "C" void kernel_launch(void* const* d_in, const int* in_sizes, int n_in,
                              void* d_out, int out_size) {
    const float* hg       = (const float*)d_in[0];
    const float* corr     = (const float*)d_in[1];
    const float* all_emb  = (const float*)d_in[2];
    const int*   sz_idx   = (const int*)d_in[3];
    const int*   nsz_idx  = (const int*)d_in[4];
    const int*   Psz_idx  = (const int*)d_in[5];
    const int*   Pnsz_idx = (const int*)d_in[6];
    float* out = (float*)d_out;

    int nrows = in_sizes[0] / L;          // 32768
    int Ns    = in_sizes[3];
    int Nn    = in_sizes[4];
    int nPsz  = in_sizes[5];
    int nPnsz = in_sizes[6];

    int Bs = (Ns + 255) / 256;
    int Bn = (Nn + 255) / 256;
    hist_kernel<<<Bs + Bn, 256>>>(sz_idx, Ns, nsz_idx, Nn, Bs);

    int Bh = SD_BLOCKS / 2;  // equal row work per branch (both scan all rows)
    rowpass_kernel<<<SD_BLOCKS, SD_THREADS>>>(hg, nrows, corr, all_emb,
                                              Psz_idx, nPsz, Pnsz_idx, nPnsz,
                                              Bh, 1.0f / (float)Ns, 1.0f / (float)Nn,
                                              out);
}

// round 16
// speedup vs baseline: 1.5510x; 1.5510x over previous
#include <cuda_runtime.h>
#include <math.h>

#define L 512
#define NCON 20
#define INV_TEMP (1.0f / 0.07f)
#define MAXROWS 32768
#define SD_BLOCKS 592   // 4 blocks/SM on 148 SMs
#define SD_THREADS 256
#define WPB (SD_THREADS / 32)
#define FULLMASK 0xffffffffu

// scratch (device globals; no allocation allowed)
// cnt arrays: zero-initialized at load; reset-on-consume in the row kernel
// keeps them all-zero at the start of every replay.
__device__ int   g_cnt0[MAXROWS];        // histogram of sz_idx
__device__ int   g_cnt1[MAXROWS];        // histogram of nsz_idx
__device__ float g_pB[SD_BLOCKS];        // per-block partials
__device__ unsigned int g_fin = 0;       // finalize counter (reset by last block)

// ---------------------------------------------------------------------------
// Kernel 1: index histograms (deterministic int atomics).
// ---------------------------------------------------------------------------
__global__ void hist_kernel(const int* __restrict__ sz_idx, int Ns,
                            const int* __restrict__ nsz_idx, int Nn, int Bs) {
    int b = blockIdx.x;
    int branch = (b >= Bs) ? 1 : 0;
    int i = (branch ? (b - Bs) : b) * (int)blockDim.x + threadIdx.x;
    if (branch) {
        if (i < Nn) atomicAdd(&g_cnt1[nsz_idx[i]], 1);
    } else {
        if (i < Ns) atomicAdd(&g_cnt0[sz_idx[i]], 1);
    }
}

// ---------------------------------------------------------------------------
// Kernel 2: branch-split, CONTIGUOUS-chunk row pass with ballot skip and
// PAIR-interleaved processing (R12's proven dual-row body, MLP=8).
// Blocks [0,Bh) -> branch 0, [Bh,grid) -> branch 1. Warp w owns rows
// [w*rpw, w*rpw+rpw) (contiguous, rpw<=32). Counts loaded in one parallel
// shot (reset-on-consume), then sampled rows processed two at a time:
//   acc += (c_a*term_a + c_b*term_b) * scale,
//   term = log den - <row,ebar>*invnorm/tau
// ~60% of rows skipped; duplicates collapse into the count weight.
// Deterministic: fixed chunk map, fixed ballot order, fixed trees,
// fixed-order last-block finalize.
// ---------------------------------------------------------------------------
__global__ void __launch_bounds__(SD_THREADS)
rowpass_kernel(const float* __restrict__ hg, int nrows,
               const float* __restrict__ corr,
               const float* __restrict__ all_emb,
               const int* __restrict__ Psz, int nPsz,
               const int* __restrict__ Pnsz, int nPnsz,
               int Bh, int rpw, float invNs, float invNn,
               float* __restrict__ out) {
    __shared__ float se[L];
    __shared__ int sp[16];
    __shared__ float sw[WPB];
    __shared__ float sh[SD_THREADS];
    __shared__ bool is_last;

    int tid = threadIdx.x;
    int branch = (blockIdx.x >= Bh) ? 1 : 0;
    const int* P = branch ? Pnsz : Psz;
    int nP = branch ? nPnsz : nPsz;
    int* cntp = branch ? g_cnt1 : g_cnt0;
    float scale = branch ? invNn : invNs;

    if (tid < nP) sp[tid] = P[tid];
    __syncthreads();

    unsigned int mask = 0u;
    for (int j = 0; j < nP; j++) mask |= 1u << sp[j];

    // build this branch's ebar into smem (nP L2-hot concept rows)
    for (int t = tid; t < L; t += SD_THREADS) {
        float s = 0.0f;
        for (int j = 0; j < nP; j++) s += all_emb[sp[j] * L + t];
        se[t] = s / (float)nP;
    }
    __syncthreads();

    int lane = tid & 31;
    int wib  = tid >> 5;
    int bb   = branch ? (blockIdx.x - Bh) : blockIdx.x;
    int nbb  = branch ? (gridDim.x - Bh) : Bh;
    int wg   = bb * WPB + wib;    // warp index within branch

    const float4* ep = reinterpret_cast<const float4*>(se);
    bool act = lane < NCON;
    float wm = (act && !((mask >> lane) & 1u)) ? 1.0f : 0.0f;

    float acc = 0.0f;
    int row0 = wg * rpw;
    if (row0 < nrows) {
        int nmine = nrows - row0;
        if (nmine > rpw) nmine = rpw;

        // one parallel shot of count loads (MLP = nmine), reset-on-consume
        int c = (lane < nmine) ? cntp[row0 + lane] : 0;
        if (c) cntp[row0 + lane] = 0;
        unsigned int bal = __ballot_sync(FULLMASK, c != 0);

        while (bal) {
            int b1 = __ffs(bal) - 1;
            bal &= bal - 1;
            int b2 = bal ? (__ffs(bal) - 1) : 0;
            bool hasb = (bal != 0);
            if (hasb) bal &= bal - 1;

            int ra = row0 + b1;
            int rb = hasb ? (row0 + b2) : ra;
            float ca = (float)__shfl_sync(FULLMASK, c, b1);
            float cb = hasb ? (float)__shfl_sync(FULLMASK, c, b2) : 0.0f;

            // denominators: lanes 0..19 handle one concept each, both rows
            float ea = act ? __expf(corr[ra * NCON + lane] * INV_TEMP) : 0.0f;
            float eb = act ? __expf(corr[rb * NCON + lane] * INV_TEMP) : 0.0f;
            float dena = ea * wm;
            float denb = eb * wm;

            const float4* rpa = reinterpret_cast<const float4*>(hg + (size_t)ra * L);
            const float4* rpb = reinterpret_cast<const float4*>(hg + (size_t)rb * L);
            float ssa = 0.0f, da = 0.0f, ssb = 0.0f, db = 0.0f;
#pragma unroll
            for (int it = 0; it < 4; it++) {
                int idx = it * 32 + lane;
                float4 va = rpa[idx];
                float4 vb = rpb[idx];
                float4 ev = ep[idx];
                ssa = fmaf(va.x, va.x, fmaf(va.y, va.y, fmaf(va.z, va.z, fmaf(va.w, va.w, ssa))));
                da  = fmaf(va.x, ev.x, fmaf(va.y, ev.y, fmaf(va.z, ev.z, fmaf(va.w, ev.w, da))));
                ssb = fmaf(vb.x, vb.x, fmaf(vb.y, vb.y, fmaf(vb.z, vb.z, fmaf(vb.w, vb.w, ssb))));
                db  = fmaf(vb.x, ev.x, fmaf(vb.y, ev.y, fmaf(vb.z, ev.z, fmaf(vb.w, ev.w, db))));
            }
#pragma unroll
            for (int o = 16; o > 0; o >>= 1) {
                ssa  += __shfl_xor_sync(FULLMASK, ssa, o);
                da   += __shfl_xor_sync(FULLMASK, da, o);
                dena += __shfl_xor_sync(FULLMASK, dena, o);
                ssb  += __shfl_xor_sync(FULLMASK, ssb, o);
                db   += __shfl_xor_sync(FULLMASK, db, o);
                denb += __shfl_xor_sync(FULLMASK, denb, o);
            }
            if (lane == 0) {
                float invna = 1.0f / fmaxf(sqrtf(ssa), 1e-12f);
                acc += ca * (__logf(dena) - da * invna * INV_TEMP) * scale;
                if (cb != 0.0f) {
                    float invnb = 1.0f / fmaxf(sqrtf(ssb), 1e-12f);
                    acc += cb * (__logf(denb) - db * invnb * INV_TEMP) * scale;
                }
            }
        }
    }

    // block partial + last-block fixed-order finalize
    if (lane == 0) sw[wib] = acc;
    __syncthreads();
    if (tid == 0) {
        float s = 0.0f;
#pragma unroll
        for (int k = 0; k < WPB; k++) s += sw[k];
        g_pB[blockIdx.x] = s;
        __threadfence();
        is_last = (atomicAdd(&g_fin, 1u) == gridDim.x - 1);
    }
    __syncthreads();

    if (is_last) {
        __threadfence();  // see all blocks' partials
        float a = 0.0f;
        for (int j = tid; j < SD_BLOCKS; j += SD_THREADS) a += g_pB[j];  // fixed order
        sh[tid] = a;
        __syncthreads();
        for (int s = 128; s > 0; s >>= 1) {
            if (tid < s) sh[tid] += sh[tid + s];
            __syncthreads();
        }
        if (tid == 0) { out[0] = sh[0]; g_fin = 0u; }
    }
}

extern "C" void kernel_launch(void* const* d_in, const int* in_sizes, int n_in,
                              void* d_out, int out_size) {
    const float* hg       = (const float*)d_in[0];
    const float* corr     = (const float*)d_in[1];
    const float* all_emb  = (const float*)d_in[2];
    const int*   sz_idx   = (const int*)d_in[3];
    const int*   nsz_idx  = (const int*)d_in[4];
    const int*   Psz_idx  = (const int*)d_in[5];
    const int*   Pnsz_idx = (const int*)d_in[6];
    float* out = (float*)d_out;

    int nrows = in_sizes[0] / L;          // 32768
    int Ns    = in_sizes[3];
    int Nn    = in_sizes[4];
    int nPsz  = in_sizes[5];
    int nPnsz = in_sizes[6];

    int Bs = (Ns + 255) / 256;
    int Bn = (Nn + 255) / 256;
    hist_kernel<<<Bs + Bn, 256>>>(sz_idx, Ns, nsz_idx, Nn, Bs);

    int Bh = SD_BLOCKS / 2;                       // 296 blocks per branch
    int wpb_branch = Bh * WPB;                    // 2368 warps per branch
    int rpw = (nrows + wpb_branch - 1) / wpb_branch;  // 14 contiguous rows/warp
    if (rpw > 32) rpw = 32;                       // safety (ballot width)

    rowpass_kernel<<<SD_BLOCKS, SD_THREADS>>>(hg, nrows, corr, all_emb,
                                              Psz_idx, nPsz, Pnsz_idx, nPnsz,
                                              Bh, rpw, 1.0f / (float)Ns, 1.0f / (float)Nn,
                                              out);
}